// round 15
// baseline (speedup 1.0000x reference)
#include <cuda_runtime.h>
#include <cuda_fp16.h>

typedef unsigned long long u64;
typedef unsigned int u32;

#define SEQ 512
#define BATCH 32
#define HID 1024
#define G4 4096
#define M_TOT 16384          /* SEQ*BATCH */
#define NB2 128              /* phase-2 persistent grid: 2 dirs x 64 */

#define WPAD 1048            /* lstm W row length (halves): 2096B stride */
#define WSLAB (64*WPAD)
#define HSLAB2 (4*32*264)    /* h slab: 4 chunks x 32 b x 264 halves */
#define CHUNKB 16896         /* bytes per h chunk (32 x 264 x 2) */

/* lstm smem byte offsets */
#define OFF_MB 0             /* mbW + 4 chunk mbarriers */
#define OFF_W  1024
#define OFF_H  (OFF_W + 64*WPAD*2)
#define OFF_XS (OFF_H + 4*CHUNKB)
#define OFF_HS (OFF_XS + 128*20*4)
#define SMEM2L (OFF_HS + 16*33*4)

/* xproj mma smem: 384 rows (128 A + 256 B) x 80B = 30720B/stage, 3 stages */
#define XSTG 30720
#define SMEMX (3*XSTG)

// scratch (device globals; no allocation allowed)
__device__ float  g_xp[(size_t)2 * M_TOT * G4];     // [dir][s*32+b][gate] fp32
__device__ __half g_wh16[(size_t)128 * WSLAB];      // lstm per-CTA W slabs
__device__ __half g_h16[4 * HSLAB2];                // [parity*2+dir][kc][b][264]
__device__ __half g_xh16[(size_t)M_TOT * HID];      // x in fp16 [b][s][k]
__device__ __half g_wi16[(size_t)2 * G4 * HID];     // W_ii fp16 [d][g][k]
__device__ u32 g_cnt;
__device__ u32 g_gen;
__device__ u32 g_prod[2][2][4][32];  // [dir][parity][chunk][pad] monotonic
__device__ u32 g_cons[2][2][32];     // [dir][parity][pad] monotonic

// ---------------- fast activations (MUFU-only) ----------------------------
__device__ __forceinline__ float sigf(float x){
    return __fdividef(1.0f, 1.0f + __expf(-x));
}
__device__ __forceinline__ float tanhfast(float x){
    return 1.0f - __fdividef(2.0f, __expf(2.0f*x) + 1.0f);
}
__device__ __forceinline__ void stcg_u32(u32* p,u32 v){
    asm volatile("st.global.cg.u32 [%0],%1;"::"l"(p),"r"(v));}
__device__ __forceinline__ void stcg_u64(void* p,u64 v){
    asm volatile("st.global.cg.u64 [%0],%1;"::"l"(p),"l"(v));}
__device__ __forceinline__ u32 ldcgu(const u32* p){
    u32 v;asm volatile("ld.global.cg.u32 %0,[%1];":"=r"(v):"l"(p));return v;}
__device__ __forceinline__ u32 smem_u32(const void* p){
    u32 a;asm("{ .reg .u64 t; cvta.to.shared.u64 t, %1; cvt.u32.u64 %0, t; }":"=r"(a):"l"(p));return a;}
__device__ __forceinline__ void red_rel(u32* p){
    asm volatile("red.release.gpu.global.add.u32 [%0],%1;"::"l"(p),"r"(1u):"memory");}
__device__ __forceinline__ u32 ld_acq(const u32* p){
    u32 v;asm volatile("ld.acquire.gpu.global.u32 %0,[%1];":"=r"(v):"l"(p));return v;}
__device__ __forceinline__ void spin_ge(const u32* p,u32 tgt){
    u32 v;
    do { v = ld_acq(p); } while ((int)(v - tgt) < 0);
}

// ---------------- mbarrier / bulk / cp.async ------------------------------
#define MINIT(mb,cnt) asm volatile("mbarrier.init.shared.b64 [%0], %1;"::"r"(mb),"r"(cnt):"memory")
#define MEXPECT(mb,tx) asm volatile("mbarrier.arrive.expect_tx.shared.b64 _, [%0], %1;"::"r"(mb),"r"(tx):"memory")
#define MWAIT(mb,ph) do{ asm volatile("{\n\t.reg .pred P1;\n\tWL%=:\n\t" \
    "mbarrier.try_wait.parity.acquire.cta.shared::cta.b64 P1, [%0], %1, 0x989680;\n\t" \
    "@P1 bra WD%=;\n\tbra WL%=;\n\tWD%=:\n\t}" :: "r"(mb), "r"(ph) : "memory"); }while(0)
#define BULK_G2S(sm,gp,sz,mb) asm volatile( \
    "cp.async.bulk.shared::cta.global.mbarrier::complete_tx::bytes [%0], [%1], %2, [%3];" \
    ::"r"(sm),"l"(gp),"r"(sz),"r"(mb):"memory")
#define CP16(dst,src) asm volatile("cp.async.cg.shared.global [%0], [%1], 16;"::"r"(dst),"l"(src):"memory")
#define CPCOMMIT() asm volatile("cp.async.commit_group;":::"memory")
#define CPWAIT0()  asm volatile("cp.async.wait_group 0;":::"memory")
#define CPWAIT1()  asm volatile("cp.async.wait_group 1;":::"memory")

__device__ __forceinline__ void ldsm4(u32& r0,u32& r1,u32& r2,u32& r3,u32 a){
    asm volatile("ldmatrix.sync.aligned.m8n8.x4.shared.b16 {%0,%1,%2,%3},[%4];"
        :"=r"(r0),"=r"(r1),"=r"(r2),"=r"(r3):"r"(a));
}
__device__ __forceinline__ void mma16816(float* c,u32 a0,u32 a1,u32 a2,u32 a3,u32 b0,u32 b1){
    asm volatile("mma.sync.aligned.m16n8k16.row.col.f32.f16.f16.f32 "
        "{%0,%1,%2,%3},{%4,%5,%6,%7},{%8,%9},{%0,%1,%2,%3};"
        :"+f"(c[0]),"+f"(c[1]),"+f"(c[2]),"+f"(c[3])
        :"r"(a0),"r"(a1),"r"(a2),"r"(a3),"r"(b0),"r"(b1));
}

// ---------------- init-only grid barrier ----------------------------------
__device__ __forceinline__ void gridbar(u32& mygen){
    __syncthreads();
    if (threadIdx.x==0){
        u32 arr;
        asm volatile("atom.release.gpu.global.add.u32 %0,[%1],%2;"
                     :"=r"(arr):"l"(&g_cnt),"r"(1u));
        if (arr == NB2-1u){
            asm volatile("st.global.cg.u32 [%0],%1;"::"l"(&g_cnt),"r"(0u));
            asm volatile("st.release.gpu.global.u32 [%0],%1;"
                         ::"l"(&g_gen),"r"(mygen+1u));
        } else {
            u32 v;
            do { asm volatile("ld.acquire.gpu.global.u32 %0,[%1];"
                              :"=r"(v):"l"(&g_gen)); } while (v==mygen);
        }
    }
    mygen++;
    __syncthreads();
}

// ---------------- fp32 -> fp16 conversion ---------------------------------
__global__ __launch_bounds__(256) void conv_kernel(
    const float* __restrict__ src, __half* __restrict__ dst, int n4)
{
    int i = blockIdx.x*blockDim.x + threadIdx.x;
    int stride = gridDim.x*blockDim.x;
    for (; i<n4; i+=stride){
        float4 v = *(const float4*)(src + (size_t)i*4);
        __half2 h0 = __floats2half2_rn(v.x, v.y);
        __half2 h1 = __floats2half2_rn(v.z, v.w);
        u32* p = (u32*)(dst + (size_t)i*4);
        p[0] = *(u32*)&h0; p[1] = *(u32*)&h1;
    }
}

// ---------------- phase 0: W_hi -> fp16 gate-interleaved slabs ------------
__global__ __launch_bounds__(256) void wprep_kernel(
    const float* __restrict__ Whf, const float* __restrict__ Whr)
{
    const int c = blockIdx.x;
    const int d = c>>6, r = c&63, j0 = r<<4;
    const float* __restrict__ W = d ? Whr : Whf;
    __half* slab = g_wh16 + (size_t)c*WSLAB;

    const int t  = threadIdx.x;
    const int ri = t >> 2;
    const int k0 = (t & 3) << 8;
    const int a = ri>>4, gate = (ri>>2)&3, du = ri&3;
    const int grow = gate*HID + j0 + a*4 + du;
    const float* src = W + (size_t)grow*HID + k0;
    u32* dst = (u32*)(slab + ri*WPAD + k0);

#pragma unroll 8
    for (int k=0;k<256;k+=4){
        float4 v = *(const float4*)(src + k);
        __half2 h0 = __floats2half2_rn(v.x, v.y);
        __half2 h1 = __floats2half2_rn(v.z, v.w);
        dst[(k>>1)  ] = *(u32*)&h0;
        dst[(k>>1)+1] = *(u32*)&h1;
    }
}

// ---------------- phase 1: xp = x . W_ii^T + b ----------------------------
// 128x256 CTA tile, 8 warps of 64x64 (wr=w>>2, wc=w&3), 3-stage cp.async.
__global__ __launch_bounds__(256,1) void xproj_mma_kernel(
    const float* __restrict__ bf, const float* __restrict__ br)
{
    extern __shared__ char xsm[];
    const u32 smb = smem_u32(xsm);
    const int t = threadIdx.x;
    const int w = t>>5, ln = t&31;
    const int d  = blockIdx.z;
    const int g0 = blockIdx.x << 8;
    const int m0 = blockIdx.y << 7;
    const float* __restrict__ bias = d ? br : bf;

    const __half* srcb[6];
    u32 dsto[6];
#pragma unroll
    for (int j=0;j<6;j++){
        const int i = t + j*256;
        const int row = i>>2, sg = i&3;
        if (row < 128){
            const int m = m0 + row;
            const int s = m>>5, b = m&31;
            const int srow = d ? (SEQ-1-s) : s;
            srcb[j] = g_xh16 + ((size_t)(b*SEQ + srow))*HID + sg*8;
        } else {
            srcb[j] = g_wi16 + ((size_t)d*G4 + g0 + (row-128))*HID + sg*8;
        }
        dsto[j] = smb + row*80 + sg*16;
    }

    const int wr = w>>2, wc = w&3;
    const u32 aL = smb + (wr*64 + (ln&15))*80 + ((ln>>4)<<4);
    const u32 bL = smb + (128 + wc*64 + (ln&7) + ((ln>>4)<<3))*80
                   + (((ln>>3)&1)<<4);

    float acc[4][8][4];
#pragma unroll
    for (int i=0;i<4;i++)
#pragma unroll
        for (int j=0;j<8;j++)
#pragma unroll
            for (int q=0;q<4;q++) acc[i][j][q]=0.0f;

#pragma unroll
    for (int pc=0;pc<2;pc++){
        const u32 bo = pc*XSTG;
#pragma unroll
        for (int j=0;j<6;j++)
            CP16(dsto[j]+bo, srcb[j] + pc*32);
        CPCOMMIT();
    }

    for (int c=0; c<32; c++){
        CPWAIT1();
        __syncthreads();
        if (c+2 < 32){
            const u32 bo = ((c+2)%3)*XSTG;
#pragma unroll
            for (int j=0;j<6;j++)
                CP16(dsto[j]+bo, srcb[j] + (c+2)*32);
        }
        CPCOMMIT();
        const u32 base = (c%3)*XSTG;
#pragma unroll
        for (int k16=0;k16<2;k16++){
            u32 aa[4][4], bb[4][4];
#pragma unroll
            for (int nt=0;nt<4;nt++)
                ldsm4(bb[nt][0],bb[nt][1],bb[nt][2],bb[nt][3],
                      bL + base + nt*1280 + k16*32);
#pragma unroll
            for (int mt=0;mt<4;mt++)
                ldsm4(aa[mt][0],aa[mt][1],aa[mt][2],aa[mt][3],
                      aL + base + mt*1280 + k16*32);
#pragma unroll
            for (int mt=0;mt<4;mt++){
#pragma unroll
                for (int nt=0;nt<4;nt++){
                    mma16816(acc[mt][nt*2  ], aa[mt][0],aa[mt][1],aa[mt][2],aa[mt][3],
                             bb[nt][0], bb[nt][1]);
                    mma16816(acc[mt][nt*2+1], aa[mt][0],aa[mt][1],aa[mt][2],aa[mt][3],
                             bb[nt][2], bb[nt][3]);
                }
            }
        }
    }

    float2 bv[8];
#pragma unroll
    for (int n8=0;n8<8;n8++)
        bv[n8] = *(const float2*)&bias[g0 + wc*64 + n8*8 + (ln&3)*2];
#pragma unroll
    for (int mt=0;mt<4;mt++){
        const int r0 = m0 + wr*64 + mt*16 + (ln>>2);
        float* o0 = g_xp + ((size_t)d*M_TOT + r0    )*G4;
        float* o1 = g_xp + ((size_t)d*M_TOT + r0 + 8)*G4;
#pragma unroll
        for (int n8=0;n8<8;n8++){
            const int col = g0 + wc*64 + n8*8 + (ln&3)*2;
            *(float2*)(o0+col) = make_float2(acc[mt][n8][0]+bv[n8].x,
                                             acc[mt][n8][1]+bv[n8].y);
            *(float2*)(o1+col) = make_float2(acc[mt][n8][2]+bv[n8].x,
                                             acc[mt][n8][3]+bv[n8].y);
        }
    }
}

// ---------------- phase 2: persistent mma.sync recurrent kernel -----------
// r13 structure; store phase reordered so the h-publish release does not
// have to drain the fp32 out-stores: h stores -> syncthreads -> t0 publish
// -> out stores -> trailing syncthreads. Arithmetic identical to r13.
__global__ __launch_bounds__(256,1) void lstm_kernel(float* __restrict__ out)
{
    extern __shared__ char sm[];
    const u32 smb = smem_u32(sm);
    const int t  = threadIdx.x;
    const int w  = t>>5, ln = t&31;
    const int cta = blockIdx.x;
    const int d = cta>>6, r = cta&63;
    const int j0 = r<<4;
    const u32 mbW = smb+OFF_MB;
    const u32 mbC0 = smb+OFF_MB+8;

    u32 bargen;
    asm volatile("ld.global.cg.u32 %0,[%1];":"=r"(bargen):"l"(&g_gen));

    u32 myPb0=0, myPb1=0, cB0=0, cB1=0;
    if (w==7 && ln<4){
        myPb0 = ldcgu(&g_prod[d][0][ln][0]);
        myPb1 = ldcgu(&g_prod[d][1][ln][0]);
    }
    if (t==0){
        cB0 = ldcgu(&g_cons[d][0][0]); cB1 = ldcgu(&g_cons[d][1][0]);
    }

    if (t==0){
        MINIT(mbW,1);
#pragma unroll
        for (int kc=0;kc<4;kc++) MINIT(mbC0+kc*8, 1);
        MEXPECT(mbW, (u32)(WSLAB*2));
        BULK_G2S(smb+OFF_W, g_wh16 + (size_t)cta*WSLAB, (u32)(WSLAB*2), mbW);
    }

    {
        u32* hz = (u32*)g_h16;
        for (int i = cta*256 + t; i < HSLAB2; i += NB2*256) stcg_u32(hz+i, 0u);
    }
    gridbar(bargen);

    MWAIT(mbW, 0u);

    const u32 aBase = smb + OFF_W + ((w>>1)*16 + (ln&15))*(WPAD*2) + ((ln>>4)<<4);
    const u32 bBase = smb + OFF_H + ((w&1)*16 + (ln&7) + ((ln>>4)<<3))*528
                      + (((ln>>3)&1)<<4);

    float* xs2   = (float*)(sm + OFF_XS);
    float* hsout = (float*)(sm + OFF_HS);

    const int q   = ln>>2;
    const int low = (q < 4);
    const int du  = q & 3;
    const int u   = ((w>>1)<<2) + du;
    const int col = ((w&1)<<4) + ((ln&3)<<1);
    const int c0i = low ? col : col+8;
    const int xb = t>>3, xg = (t&7)>>1, xh = (t&1);
    const u32 xsDst = smb + OFF_XS + ((xg*32+xb)*20 + xh*8)*4;
    const int mykc = r>>4;
    const int st   = (mykc+1)&3;

    float cst0 = 0.0f, cst1 = 0.0f;

    for (int s=0; s<SEQ; s++){
        const int cur = s&1, nxt = cur^1;
        const u32 rnd = (u32)((s+1)>>1);

        if (w==7){
            const char* hbase = (const char*)(g_h16 + (size_t)(cur*2+d)*HSLAB2);
            bool need = (ln<4);
            const u32 tgt = (cur?myPb1:myPb0) + 16u*rnd;
            while (__any_sync(0xffffffffu, need)){
                if (need){
                    u32 v = ld_acq(&g_prod[d][cur][ln][0]);
                    if ((int)(v-tgt) >= 0){
                        MEXPECT(mbC0+ln*8, (u32)CHUNKB);
                        BULK_G2S(smb+OFF_H+ln*CHUNKB,
                                 hbase + (size_t)ln*CHUNKB,
                                 (u32)CHUNKB, mbC0+ln*8);
                        need = false;
                    }
                }
            }
        }

        {
            const float* xsrc = g_xp + ((size_t)d*M_TOT + (size_t)s*BATCH + xb)*G4
                               + xg*HID + j0 + xh*8;
            CP16(xsDst,    xsrc);
            CP16(xsDst+16, xsrc+4);
            CPCOMMIT();
        }

        float acc[2][2][4];
#pragma unroll
        for (int p1=0;p1<2;p1++)
#pragma unroll
            for (int p2=0;p2<2;p2++)
#pragma unroll
                for (int p3=0;p3<4;p3++) acc[p1][p2][p3]=0.0f;

#pragma unroll
        for (int i=0;i<4;i++){
            const int kc = (st+i)&3;
            MWAIT(mbC0+kc*8, (u32)(s&1));
            if (i==3 && t==0) red_rel(&g_cons[d][cur][0]);
            const u32 aC = aBase + (u32)(kc*512);
            const u32 bC = bBase + (u32)(kc*CHUNKB);
            u32 a0,a1,a2,a3,b0,b1,b2,b3;
            ldsm4(a0,a1,a2,a3, aC);
            ldsm4(b0,b1,b2,b3, bC);
#pragma unroll
            for (int kl=0;kl<15;kl++){
                u32 na0,na1,na2,na3,nb0,nb1,nb2,nb3;
                ldsm4(na0,na1,na2,na3, aC + ((kl+1)<<5));
                ldsm4(nb0,nb1,nb2,nb3, bC + ((kl+1)<<5));
                mma16816(acc[kl&1][0], a0,a1,a2,a3, b0,b1);
                mma16816(acc[kl&1][1], a0,a1,a2,a3, b2,b3);
                a0=na0;a1=na1;a2=na2;a3=na3;
                b0=nb0;b1=nb1;b2=nb2;b3=nb3;
            }
            mma16816(acc[1][0], a0,a1,a2,a3, b0,b1);
            mma16816(acc[1][1], a0,a1,a2,a3, b2,b3);
        }

        float F0[4], F1[4];
#pragma unroll
        for (int p3=0;p3<4;p3++){
            F0[p3] = acc[0][0][p3] + acc[1][0][p3];
            F1[p3] = acc[0][1][p3] + acc[1][1][p3];
        }

        CPWAIT0();
        const int gA = q>>2;
        float A0 = F0[0] + xs2[((gA  )*32 + col  )*20 + u];
        float A1 = F0[1] + xs2[((gA  )*32 + col+1)*20 + u];
        float A2 = F1[0] + xs2[((gA  )*32 + col+8)*20 + u];
        float A3 = F1[1] + xs2[((gA  )*32 + col+9)*20 + u];
        float B0 = F0[2] + xs2[((gA+2)*32 + col  )*20 + u];
        float B1 = F0[3] + xs2[((gA+2)*32 + col+1)*20 + u];
        float B2 = F1[2] + xs2[((gA+2)*32 + col+8)*20 + u];
        float B3 = F1[3] + xs2[((gA+2)*32 + col+9)*20 + u];

        float P0 = low ? A2 : A0;
        float P1 = low ? A3 : A1;
        float P2 = low ? B2 : B0;
        float P3 = low ? B3 : B1;
        P0 = __shfl_xor_sync(0xffffffffu, P0, 16);
        P1 = __shfl_xor_sync(0xffffffffu, P1, 16);
        P2 = __shfl_xor_sync(0xffffffffu, P2, 16);
        P3 = __shfl_xor_sync(0xffffffffu, P3, 16);

        float iv0 = low ? A0 : P0,  iv1 = low ? A1 : P1;
        float gv0 = low ? B0 : P2,  gv1 = low ? B1 : P3;
        float fv0 = low ? P0 : A2,  fv1 = low ? P1 : A3;
        float ov0 = low ? P2 : B2,  ov1 = low ? P3 : B3;

        cst0 = sigf(fv0)*cst0 + sigf(iv0)*tanhfast(gv0);
        cst1 = sigf(fv1)*cst1 + sigf(iv1)*tanhfast(gv1);
        float h0 = sigf(ov0)*tanhfast(cst0);
        float h1 = sigf(ov1)*tanhfast(cst1);
        hsout[u*33 + c0i    ] = h0;
        hsout[u*33 + c0i + 1] = h1;

        if (t==0 && s>0)
            spin_ge(&g_cons[d][nxt][0], (nxt?cB1:cB0) + 64u*rnd);
        __syncthreads();

        // phase 1: h stores (t>=128); t<128 read hsout into regs only
        const int sout = d ? (SEQ-1-s) : s;
        float4 ov; float* oaddr = 0;
        if (t < 128){
            const int b = t>>2, u4 = (t&3)<<2;
            ov.x = hsout[(u4  )*33 + b];
            ov.y = hsout[(u4+1)*33 + b];
            ov.z = hsout[(u4+2)*33 + b];
            ov.w = hsout[(u4+3)*33 + b];
            oaddr = out + ((size_t)b*SEQ + sout)*(2*HID) + d*HID + j0 + u4;
        } else {
            const int t2 = t-128;
            const int b = t2>>2, u4 = (t2&3)<<2;
            __half2 ha = __floats2half2_rn(hsout[(u4  )*33+b], hsout[(u4+1)*33+b]);
            __half2 hb = __floats2half2_rn(hsout[(u4+2)*33+b], hsout[(u4+3)*33+b]);
            u64 pk = ((u64)(*(u32*)&hb) << 32) | (u64)(*(u32*)&ha);
            stcg_u64(g_h16 + (size_t)(nxt*2+d)*HSLAB2
                     + (size_t)(mykc*32 + b)*264 + (j0&255) + u4, pk);
        }
        __syncthreads();                     // h stores CTA-complete
        if (t==0) red_rel(&g_prod[d][nxt][mykc][0]);   // publish (h only)
        if (t < 128) *(float4*)oaddr = ov;   // out stores off publish path
        __syncthreads();                     // trailing (r13 invariant)
    }
}

// ---------------- launcher -------------------------------------------------
extern "C" void kernel_launch(void* const* d_in, const int* in_sizes, int n_in,
                              void* d_out, int out_size)
{
    const float* x    = (const float*)d_in[0];
    const float* Wii  = (const float*)d_in[1];
    const float* Whi  = (const float*)d_in[2];
    const float* bi   = (const float*)d_in[3];
    const float* WiiR = (const float*)d_in[4];
    const float* WhiR = (const float*)d_in[5];
    const float* biR  = (const float*)d_in[6];
    float* out = (float*)d_out;

    cudaFuncSetAttribute(lstm_kernel,
        cudaFuncAttributeMaxDynamicSharedMemorySize, SMEM2L);
    cudaFuncSetAttribute(xproj_mma_kernel,
        cudaFuncAttributeMaxDynamicSharedMemorySize, SMEMX);

    __half* xh; cudaGetSymbolAddress((void**)&xh, g_xh16);
    __half* wi; cudaGetSymbolAddress((void**)&wi, g_wi16);
    conv_kernel<<<2048, 256>>>(x,    xh,                  M_TOT*HID/4);
    conv_kernel<<<1024, 256>>>(Wii,  wi,                  G4*HID/4);
    conv_kernel<<<1024, 256>>>(WiiR, wi + (size_t)G4*HID, G4*HID/4);
    wprep_kernel<<<128, 256>>>(Whi, WhiR);

    dim3 g1(G4/256, M_TOT/128, 2);
    xproj_mma_kernel<<<g1, 256, SMEMX>>>(bi, biR);
    lstm_kernel<<<NB2, 256, SMEM2L>>>(out);
}

// round 16
// speedup vs baseline: 1.0091x; 1.0091x over previous
#include <cuda_runtime.h>
#include <cuda_fp16.h>

typedef unsigned long long u64;
typedef unsigned int u32;

#define SEQ 512
#define BATCH 32
#define HID 1024
#define G4 4096
#define M_TOT 16384          /* SEQ*BATCH */
#define NB2 128              /* phase-2 persistent grid: 2 dirs x 64 */

#define WPAD 1048            /* lstm W row length (halves): 2096B stride */
#define WSLAB (64*WPAD)
#define HSLAB2 (4*32*264)    /* h slab: 4 chunks x 32 b x 264 halves */
#define CHUNKB 16896         /* bytes per h chunk (32 x 264 x 2) */

/* lstm smem byte offsets */
#define OFF_MB 0             /* mbW + 4 chunk mbarriers */
#define OFF_W  1024
#define OFF_H  (OFF_W + 64*WPAD*2)
#define OFF_XS (OFF_H + 4*CHUNKB)
#define OFF_HS (OFF_XS + 128*20*4)
#define SMEM2L (OFF_HS + 16*33*4)

/* xproj mma smem: 384 rows (128 A + 256 B) x 80B = 30720B/stage, 3 stages */
#define XSTG 30720
#define SMEMX (3*XSTG)

// scratch (device globals; no allocation allowed)
__device__ float  g_xp[(size_t)2 * M_TOT * G4];     // [dir][s*32+b][gate] fp32
__device__ __half g_wh16[(size_t)128 * WSLAB];      // lstm per-CTA W slabs
__device__ __half g_h16[4 * HSLAB2];                // [parity*2+dir][kc][b][264]
__device__ __half g_xh16[(size_t)M_TOT * HID];      // x in fp16 [b][s][k]
__device__ __half g_wi16[(size_t)2 * G4 * HID];     // W_ii fp16 [d][g][k]
__device__ u32 g_cnt;
__device__ u32 g_gen;
__device__ u32 g_prod[2][2][4][32];  // [dir][parity][chunk][pad] monotonic
__device__ u32 g_cons[2][2][32];     // [dir][parity][pad] monotonic

// ---------------- fast activations (MUFU-only) ----------------------------
__device__ __forceinline__ float sigf(float x){
    return __fdividef(1.0f, 1.0f + __expf(-x));
}
__device__ __forceinline__ float tanhfast(float x){
    return 1.0f - __fdividef(2.0f, __expf(2.0f*x) + 1.0f);
}
__device__ __forceinline__ void stcg_u32(u32* p,u32 v){
    asm volatile("st.global.cg.u32 [%0],%1;"::"l"(p),"r"(v));}
__device__ __forceinline__ void stcg_u64(void* p,u64 v){
    asm volatile("st.global.cg.u64 [%0],%1;"::"l"(p),"l"(v));}
__device__ __forceinline__ u32 ldcgu(const u32* p){
    u32 v;asm volatile("ld.global.cg.u32 %0,[%1];":"=r"(v):"l"(p));return v;}
__device__ __forceinline__ u32 smem_u32(const void* p){
    u32 a;asm("{ .reg .u64 t; cvta.to.shared.u64 t, %1; cvt.u32.u64 %0, t; }":"=r"(a):"l"(p));return a;}
__device__ __forceinline__ void red_rel(u32* p){
    asm volatile("red.release.gpu.global.add.u32 [%0],%1;"::"l"(p),"r"(1u):"memory");}
__device__ __forceinline__ u32 ld_acq(const u32* p){
    u32 v;asm volatile("ld.acquire.gpu.global.u32 %0,[%1];":"=r"(v):"l"(p));return v;}
__device__ __forceinline__ void spin_ge(const u32* p,u32 tgt){
    u32 v;
    do { v = ld_acq(p); } while ((int)(v - tgt) < 0);
}

// ---------------- mbarrier / bulk / cp.async ------------------------------
#define MINIT(mb,cnt) asm volatile("mbarrier.init.shared.b64 [%0], %1;"::"r"(mb),"r"(cnt):"memory")
#define MEXPECT(mb,tx) asm volatile("mbarrier.arrive.expect_tx.shared.b64 _, [%0], %1;"::"r"(mb),"r"(tx):"memory")
#define MWAIT(mb,ph) do{ asm volatile("{\n\t.reg .pred P1;\n\tWL%=:\n\t" \
    "mbarrier.try_wait.parity.acquire.cta.shared::cta.b64 P1, [%0], %1, 0x989680;\n\t" \
    "@P1 bra WD%=;\n\tbra WL%=;\n\tWD%=:\n\t}" :: "r"(mb), "r"(ph) : "memory"); }while(0)
#define BULK_G2S(sm,gp,sz,mb) asm volatile( \
    "cp.async.bulk.shared::cta.global.mbarrier::complete_tx::bytes [%0], [%1], %2, [%3];" \
    ::"r"(sm),"l"(gp),"r"(sz),"r"(mb):"memory")
#define CP16(dst,src) asm volatile("cp.async.cg.shared.global [%0], [%1], 16;"::"r"(dst),"l"(src):"memory")
#define CPCOMMIT() asm volatile("cp.async.commit_group;":::"memory")
#define CPWAIT0()  asm volatile("cp.async.wait_group 0;":::"memory")
#define CPWAIT1()  asm volatile("cp.async.wait_group 1;":::"memory")

__device__ __forceinline__ void ldsm4(u32& r0,u32& r1,u32& r2,u32& r3,u32 a){
    asm volatile("ldmatrix.sync.aligned.m8n8.x4.shared.b16 {%0,%1,%2,%3},[%4];"
        :"=r"(r0),"=r"(r1),"=r"(r2),"=r"(r3):"r"(a));
}
__device__ __forceinline__ void mma16816(float* c,u32 a0,u32 a1,u32 a2,u32 a3,u32 b0,u32 b1){
    asm volatile("mma.sync.aligned.m16n8k16.row.col.f32.f16.f16.f32 "
        "{%0,%1,%2,%3},{%4,%5,%6,%7},{%8,%9},{%0,%1,%2,%3};"
        :"+f"(c[0]),"+f"(c[1]),"+f"(c[2]),"+f"(c[3])
        :"r"(a0),"r"(a1),"r"(a2),"r"(a3),"r"(b0),"r"(b1));
}

// ---------------- init-only grid barrier ----------------------------------
__device__ __forceinline__ void gridbar(u32& mygen){
    __syncthreads();
    if (threadIdx.x==0){
        u32 arr;
        asm volatile("atom.release.gpu.global.add.u32 %0,[%1],%2;"
                     :"=r"(arr):"l"(&g_cnt),"r"(1u));
        if (arr == NB2-1u){
            asm volatile("st.global.cg.u32 [%0],%1;"::"l"(&g_cnt),"r"(0u));
            asm volatile("st.release.gpu.global.u32 [%0],%1;"
                         ::"l"(&g_gen),"r"(mygen+1u));
        } else {
            u32 v;
            do { asm volatile("ld.acquire.gpu.global.u32 %0,[%1];"
                              :"=r"(v):"l"(&g_gen)); } while (v==mygen);
        }
    }
    mygen++;
    __syncthreads();
}

// ---------------- fp32 -> fp16 conversion ---------------------------------
__global__ __launch_bounds__(256) void conv_kernel(
    const float* __restrict__ src, __half* __restrict__ dst, int n4)
{
    int i = blockIdx.x*blockDim.x + threadIdx.x;
    int stride = gridDim.x*blockDim.x;
    for (; i<n4; i+=stride){
        float4 v = *(const float4*)(src + (size_t)i*4);
        __half2 h0 = __floats2half2_rn(v.x, v.y);
        __half2 h1 = __floats2half2_rn(v.z, v.w);
        u32* p = (u32*)(dst + (size_t)i*4);
        p[0] = *(u32*)&h0; p[1] = *(u32*)&h1;
    }
}

// ---------------- phase 0: W_hi -> fp16 gate-interleaved slabs ------------
__global__ __launch_bounds__(256) void wprep_kernel(
    const float* __restrict__ Whf, const float* __restrict__ Whr)
{
    const int c = blockIdx.x;
    const int d = c>>6, r = c&63, j0 = r<<4;
    const float* __restrict__ W = d ? Whr : Whf;
    __half* slab = g_wh16 + (size_t)c*WSLAB;

    const int t  = threadIdx.x;
    const int ri = t >> 2;
    const int k0 = (t & 3) << 8;
    const int a = ri>>4, gate = (ri>>2)&3, du = ri&3;
    const int grow = gate*HID + j0 + a*4 + du;
    const float* src = W + (size_t)grow*HID + k0;
    u32* dst = (u32*)(slab + ri*WPAD + k0);

#pragma unroll 8
    for (int k=0;k<256;k+=4){
        float4 v = *(const float4*)(src + k);
        __half2 h0 = __floats2half2_rn(v.x, v.y);
        __half2 h1 = __floats2half2_rn(v.z, v.w);
        dst[(k>>1)  ] = *(u32*)&h0;
        dst[(k>>1)+1] = *(u32*)&h1;
    }
}

// ---------------- phase 1: xp = x . W_ii^T + b ----------------------------
// 128x256 CTA tile, 8 warps of 64x64 (wr=w>>2, wc=w&3), 3-stage cp.async.
__global__ __launch_bounds__(256,1) void xproj_mma_kernel(
    const float* __restrict__ bf, const float* __restrict__ br)
{
    extern __shared__ char xsm[];
    const u32 smb = smem_u32(xsm);
    const int t = threadIdx.x;
    const int w = t>>5, ln = t&31;
    const int d  = blockIdx.z;
    const int g0 = blockIdx.x << 8;
    const int m0 = blockIdx.y << 7;
    const float* __restrict__ bias = d ? br : bf;

    const __half* srcb[6];
    u32 dsto[6];
#pragma unroll
    for (int j=0;j<6;j++){
        const int i = t + j*256;
        const int row = i>>2, sg = i&3;
        if (row < 128){
            const int m = m0 + row;
            const int s = m>>5, b = m&31;
            const int srow = d ? (SEQ-1-s) : s;
            srcb[j] = g_xh16 + ((size_t)(b*SEQ + srow))*HID + sg*8;
        } else {
            srcb[j] = g_wi16 + ((size_t)d*G4 + g0 + (row-128))*HID + sg*8;
        }
        dsto[j] = smb + row*80 + sg*16;
    }

    const int wr = w>>2, wc = w&3;
    const u32 aL = smb + (wr*64 + (ln&15))*80 + ((ln>>4)<<4);
    const u32 bL = smb + (128 + wc*64 + (ln&7) + ((ln>>4)<<3))*80
                   + (((ln>>3)&1)<<4);

    float acc[4][8][4];
#pragma unroll
    for (int i=0;i<4;i++)
#pragma unroll
        for (int j=0;j<8;j++)
#pragma unroll
            for (int q=0;q<4;q++) acc[i][j][q]=0.0f;

#pragma unroll
    for (int pc=0;pc<2;pc++){
        const u32 bo = pc*XSTG;
#pragma unroll
        for (int j=0;j<6;j++)
            CP16(dsto[j]+bo, srcb[j] + pc*32);
        CPCOMMIT();
    }

    for (int c=0; c<32; c++){
        CPWAIT1();
        __syncthreads();
        if (c+2 < 32){
            const u32 bo = ((c+2)%3)*XSTG;
#pragma unroll
            for (int j=0;j<6;j++)
                CP16(dsto[j]+bo, srcb[j] + (c+2)*32);
        }
        CPCOMMIT();
        const u32 base = (c%3)*XSTG;
#pragma unroll
        for (int k16=0;k16<2;k16++){
            u32 aa[4][4], bb[4][4];
#pragma unroll
            for (int nt=0;nt<4;nt++)
                ldsm4(bb[nt][0],bb[nt][1],bb[nt][2],bb[nt][3],
                      bL + base + nt*1280 + k16*32);
#pragma unroll
            for (int mt=0;mt<4;mt++)
                ldsm4(aa[mt][0],aa[mt][1],aa[mt][2],aa[mt][3],
                      aL + base + mt*1280 + k16*32);
#pragma unroll
            for (int mt=0;mt<4;mt++){
#pragma unroll
                for (int nt=0;nt<4;nt++){
                    mma16816(acc[mt][nt*2  ], aa[mt][0],aa[mt][1],aa[mt][2],aa[mt][3],
                             bb[nt][0], bb[nt][1]);
                    mma16816(acc[mt][nt*2+1], aa[mt][0],aa[mt][1],aa[mt][2],aa[mt][3],
                             bb[nt][2], bb[nt][3]);
                }
            }
        }
    }

    float2 bv[8];
#pragma unroll
    for (int n8=0;n8<8;n8++)
        bv[n8] = *(const float2*)&bias[g0 + wc*64 + n8*8 + (ln&3)*2];
#pragma unroll
    for (int mt=0;mt<4;mt++){
        const int r0 = m0 + wr*64 + mt*16 + (ln>>2);
        float* o0 = g_xp + ((size_t)d*M_TOT + r0    )*G4;
        float* o1 = g_xp + ((size_t)d*M_TOT + r0 + 8)*G4;
#pragma unroll
        for (int n8=0;n8<8;n8++){
            const int col = g0 + wc*64 + n8*8 + (ln&3)*2;
            *(float2*)(o0+col) = make_float2(acc[mt][n8][0]+bv[n8].x,
                                             acc[mt][n8][1]+bv[n8].y);
            *(float2*)(o1+col) = make_float2(acc[mt][n8][2]+bv[n8].x,
                                             acc[mt][n8][3]+bv[n8].y);
        }
    }
}

// ---------------- phase 2: persistent mma.sync recurrent kernel -----------
// r15 structure; consumed-guard moved from t0-spin-before-midsync to a
// per-storing-thread self-guard (t>=128 spin right before their h store).
// Publish (t0 release) still follows the post-store syncthreads.
__global__ __launch_bounds__(256,1) void lstm_kernel(float* __restrict__ out)
{
    extern __shared__ char sm[];
    const u32 smb = smem_u32(sm);
    const int t  = threadIdx.x;
    const int w  = t>>5, ln = t&31;
    const int cta = blockIdx.x;
    const int d = cta>>6, r = cta&63;
    const int j0 = r<<4;
    const u32 mbW = smb+OFF_MB;
    const u32 mbC0 = smb+OFF_MB+8;

    u32 bargen;
    asm volatile("ld.global.cg.u32 %0,[%1];":"=r"(bargen):"l"(&g_gen));

    u32 myPb0=0, myPb1=0;
    if (w==7 && ln<4){
        myPb0 = ldcgu(&g_prod[d][0][ln][0]);
        myPb1 = ldcgu(&g_prod[d][1][ln][0]);
    }
    // cons baselines needed by all storing threads (and t0)
    const u32 cB0 = ldcgu(&g_cons[d][0][0]);
    const u32 cB1 = ldcgu(&g_cons[d][1][0]);

    if (t==0){
        MINIT(mbW,1);
#pragma unroll
        for (int kc=0;kc<4;kc++) MINIT(mbC0+kc*8, 1);
        MEXPECT(mbW, (u32)(WSLAB*2));
        BULK_G2S(smb+OFF_W, g_wh16 + (size_t)cta*WSLAB, (u32)(WSLAB*2), mbW);
    }

    {
        u32* hz = (u32*)g_h16;
        for (int i = cta*256 + t; i < HSLAB2; i += NB2*256) stcg_u32(hz+i, 0u);
    }
    gridbar(bargen);

    MWAIT(mbW, 0u);

    const u32 aBase = smb + OFF_W + ((w>>1)*16 + (ln&15))*(WPAD*2) + ((ln>>4)<<4);
    const u32 bBase = smb + OFF_H + ((w&1)*16 + (ln&7) + ((ln>>4)<<3))*528
                      + (((ln>>3)&1)<<4);

    float* xs2   = (float*)(sm + OFF_XS);
    float* hsout = (float*)(sm + OFF_HS);

    const int q   = ln>>2;
    const int low = (q < 4);
    const int du  = q & 3;
    const int u   = ((w>>1)<<2) + du;
    const int col = ((w&1)<<4) + ((ln&3)<<1);
    const int c0i = low ? col : col+8;
    const int xb = t>>3, xg = (t&7)>>1, xh = (t&1);
    const u32 xsDst = smb + OFF_XS + ((xg*32+xb)*20 + xh*8)*4;
    const int mykc = r>>4;
    const int st   = (mykc+1)&3;

    float cst0 = 0.0f, cst1 = 0.0f;

    for (int s=0; s<SEQ; s++){
        const int cur = s&1, nxt = cur^1;
        const u32 rnd = (u32)((s+1)>>1);

        if (w==7){
            const char* hbase = (const char*)(g_h16 + (size_t)(cur*2+d)*HSLAB2);
            bool need = (ln<4);
            const u32 tgt = (cur?myPb1:myPb0) + 16u*rnd;
            while (__any_sync(0xffffffffu, need)){
                if (need){
                    u32 v = ld_acq(&g_prod[d][cur][ln][0]);
                    if ((int)(v-tgt) >= 0){
                        MEXPECT(mbC0+ln*8, (u32)CHUNKB);
                        BULK_G2S(smb+OFF_H+ln*CHUNKB,
                                 hbase + (size_t)ln*CHUNKB,
                                 (u32)CHUNKB, mbC0+ln*8);
                        need = false;
                    }
                }
            }
        }

        {
            const float* xsrc = g_xp + ((size_t)d*M_TOT + (size_t)s*BATCH + xb)*G4
                               + xg*HID + j0 + xh*8;
            CP16(xsDst,    xsrc);
            CP16(xsDst+16, xsrc+4);
            CPCOMMIT();
        }

        float acc[2][2][4];
#pragma unroll
        for (int p1=0;p1<2;p1++)
#pragma unroll
            for (int p2=0;p2<2;p2++)
#pragma unroll
                for (int p3=0;p3<4;p3++) acc[p1][p2][p3]=0.0f;

#pragma unroll
        for (int i=0;i<4;i++){
            const int kc = (st+i)&3;
            MWAIT(mbC0+kc*8, (u32)(s&1));
            if (i==3 && t==0) red_rel(&g_cons[d][cur][0]);
            const u32 aC = aBase + (u32)(kc*512);
            const u32 bC = bBase + (u32)(kc*CHUNKB);
            u32 a0,a1,a2,a3,b0,b1,b2,b3;
            ldsm4(a0,a1,a2,a3, aC);
            ldsm4(b0,b1,b2,b3, bC);
#pragma unroll
            for (int kl=0;kl<15;kl++){
                u32 na0,na1,na2,na3,nb0,nb1,nb2,nb3;
                ldsm4(na0,na1,na2,na3, aC + ((kl+1)<<5));
                ldsm4(nb0,nb1,nb2,nb3, bC + ((kl+1)<<5));
                mma16816(acc[kl&1][0], a0,a1,a2,a3, b0,b1);
                mma16816(acc[kl&1][1], a0,a1,a2,a3, b2,b3);
                a0=na0;a1=na1;a2=na2;a3=na3;
                b0=nb0;b1=nb1;b2=nb2;b3=nb3;
            }
            mma16816(acc[1][0], a0,a1,a2,a3, b0,b1);
            mma16816(acc[1][1], a0,a1,a2,a3, b2,b3);
        }

        float F0[4], F1[4];
#pragma unroll
        for (int p3=0;p3<4;p3++){
            F0[p3] = acc[0][0][p3] + acc[1][0][p3];
            F1[p3] = acc[0][1][p3] + acc[1][1][p3];
        }

        CPWAIT0();
        const int gA = q>>2;
        float A0 = F0[0] + xs2[((gA  )*32 + col  )*20 + u];
        float A1 = F0[1] + xs2[((gA  )*32 + col+1)*20 + u];
        float A2 = F1[0] + xs2[((gA  )*32 + col+8)*20 + u];
        float A3 = F1[1] + xs2[((gA  )*32 + col+9)*20 + u];
        float B0 = F0[2] + xs2[((gA+2)*32 + col  )*20 + u];
        float B1 = F0[3] + xs2[((gA+2)*32 + col+1)*20 + u];
        float B2 = F1[2] + xs2[((gA+2)*32 + col+8)*20 + u];
        float B3 = F1[3] + xs2[((gA+2)*32 + col+9)*20 + u];

        float P0 = low ? A2 : A0;
        float P1 = low ? A3 : A1;
        float P2 = low ? B2 : B0;
        float P3 = low ? B3 : B1;
        P0 = __shfl_xor_sync(0xffffffffu, P0, 16);
        P1 = __shfl_xor_sync(0xffffffffu, P1, 16);
        P2 = __shfl_xor_sync(0xffffffffu, P2, 16);
        P3 = __shfl_xor_sync(0xffffffffu, P3, 16);

        float iv0 = low ? A0 : P0,  iv1 = low ? A1 : P1;
        float gv0 = low ? B0 : P2,  gv1 = low ? B1 : P3;
        float fv0 = low ? P0 : A2,  fv1 = low ? P1 : A3;
        float ov0 = low ? P2 : B2,  ov1 = low ? P3 : B3;

        cst0 = sigf(fv0)*cst0 + sigf(iv0)*tanhfast(gv0);
        cst1 = sigf(fv1)*cst1 + sigf(iv1)*tanhfast(gv1);
        float h0 = sigf(ov0)*tanhfast(cst0);
        float h1 = sigf(ov1)*tanhfast(cst1);
        hsout[u*33 + c0i    ] = h0;
        hsout[u*33 + c0i + 1] = h1;

        __syncthreads();

        // phase 1: h stores (t>=128, each self-guarded); t<128 prep out regs
        const int sout = d ? (SEQ-1-s) : s;
        float4 ovv; float* oaddr = 0;
        if (t < 128){
            const int b = t>>2, u4 = (t&3)<<2;
            ovv.x = hsout[(u4  )*33 + b];
            ovv.y = hsout[(u4+1)*33 + b];
            ovv.z = hsout[(u4+2)*33 + b];
            ovv.w = hsout[(u4+3)*33 + b];
            oaddr = out + ((size_t)b*SEQ + sout)*(2*HID) + d*HID + j0 + u4;
        } else {
            const int t2 = t-128;
            const int b = t2>>2, u4 = (t2&3)<<2;
            __half2 ha = __floats2half2_rn(hsout[(u4  )*33+b], hsout[(u4+1)*33+b]);
            __half2 hb = __floats2half2_rn(hsout[(u4+2)*33+b], hsout[(u4+3)*33+b]);
            u64 pk = ((u64)(*(u32*)&hb) << 32) | (u64)(*(u32*)&ha);
            if (s>0) spin_ge(&g_cons[d][nxt][0], (nxt?cB1:cB0) + 64u*rnd);
            stcg_u64(g_h16 + (size_t)(nxt*2+d)*HSLAB2
                     + (size_t)(mykc*32 + b)*264 + (j0&255) + u4, pk);
        }
        __syncthreads();                     // h stores CTA-complete
        if (t==0) red_rel(&g_prod[d][nxt][mykc][0]);   // publish (h only)
        if (t < 128) *(float4*)oaddr = ovv;  // out stores off publish path
        __syncthreads();                     // trailing (buffer-reuse fence)
    }
}

// ---------------- launcher -------------------------------------------------
extern "C" void kernel_launch(void* const* d_in, const int* in_sizes, int n_in,
                              void* d_out, int out_size)
{
    const float* x    = (const float*)d_in[0];
    const float* Wii  = (const float*)d_in[1];
    const float* Whi  = (const float*)d_in[2];
    const float* bi   = (const float*)d_in[3];
    const float* WiiR = (const float*)d_in[4];
    const float* WhiR = (const float*)d_in[5];
    const float* biR  = (const float*)d_in[6];
    float* out = (float*)d_out;

    cudaFuncSetAttribute(lstm_kernel,
        cudaFuncAttributeMaxDynamicSharedMemorySize, SMEM2L);
    cudaFuncSetAttribute(xproj_mma_kernel,
        cudaFuncAttributeMaxDynamicSharedMemorySize, SMEMX);

    __half* xh; cudaGetSymbolAddress((void**)&xh, g_xh16);
    __half* wi; cudaGetSymbolAddress((void**)&wi, g_wi16);
    conv_kernel<<<2048, 256>>>(x,    xh,                  M_TOT*HID/4);
    conv_kernel<<<1024, 256>>>(Wii,  wi,                  G4*HID/4);
    conv_kernel<<<1024, 256>>>(WiiR, wi + (size_t)G4*HID, G4*HID/4);
    wprep_kernel<<<128, 256>>>(Whi, WhiR);

    dim3 g1(G4/256, M_TOT/128, 2);
    xproj_mma_kernel<<<g1, 256, SMEMX>>>(bi, biR);
    lstm_kernel<<<NB2, 256, SMEM2L>>>(out);
}